// round 2
// baseline (speedup 1.0000x reference)
#include <cuda_runtime.h>
#include <cuda_bf16.h>

#define NN 1000000
#define NE 16000000
#define MAX_IT 100

// ---- device scratch (allocation-free rule: __device__ globals) ----
__device__ int2  g_edges[NE];      // packed (row, col) as int32
__device__ int   g_deg[NN];        // out-degree counts
__device__ float g_w[NN];          // alpha / deg
__device__ float g_y[NN];          // v * w  (per-iteration gather source)
__device__ float g_nv[NN];         // new_v accumulator
__device__ float g_err[MAX_IT + 1];
__device__ unsigned g_barcnt;      // grid barrier arrival count
__device__ unsigned g_sense;       // grid barrier generation

// Software grid barrier (all blocks co-resident by construction).
// __threadfence() is gpu-scope -> CCTL.IVALL on sm_103a, so plain loads
// after the barrier observe other SMs' writes (no stale L1).
__device__ __forceinline__ void grid_bar(int nblocks) {
    __syncthreads();
    if (threadIdx.x == 0) {
        unsigned gen = *((volatile unsigned*)&g_sense);
        __threadfence();  // release this block's writes before arriving
        unsigned a = atomicAdd(&g_barcnt, 1u);
        if (a == (unsigned)(nblocks - 1)) {
            g_barcnt = 0;
            __threadfence();
            atomicExch(&g_sense, gen + 1u);
        } else {
            while (*((volatile unsigned*)&g_sense) == gen) { __nanosleep(64); }
        }
        __threadfence();  // acquire: invalidate L1 before post-barrier reads
    }
    __syncthreads();
}

__device__ __forceinline__ float block_reduce_sum(float v) {
    __shared__ float sh[32];
    int lane = threadIdx.x & 31;
    int wid  = threadIdx.x >> 5;
    #pragma unroll
    for (int o = 16; o; o >>= 1) v += __shfl_down_sync(0xffffffffu, v, o);
    if (lane == 0) sh[wid] = v;
    __syncthreads();
    if (wid == 0) {
        v = (lane < (int)(blockDim.x >> 5)) ? sh[lane] : 0.0f;
        #pragma unroll
        for (int o = 16; o; o >>= 1) v += __shfl_down_sync(0xffffffffu, v, o);
    }
    return v;  // valid in warp 0; next grid_bar's __syncthreads guards sh reuse
}

__global__ void __launch_bounds__(512)
pagerank_persistent(const void* __restrict__ ei_raw, float* __restrict__ v,
                    int nblocks) {
    const int gsize = gridDim.x * blockDim.x;
    const int gtid  = blockIdx.x * blockDim.x + threadIdx.x;

    const float inv_n    = 1.0f / (float)NN;
    const float teleport = 0.15f * inv_n;
    const float thresh   = 1000000.0f * 1e-6f;  // N * TOL in float32

    // ---- dtype sniff: int64 vs int32 edge_index -------------------------
    // Genuine int64 indices are all in [0, NN). An int32 buffer read as
    // int64 pairs gives lo + hi*2^32 with hi a random index in [0, 1M):
    // value < NN only if hi==0 (p ~ 1e-6 per element). 8 checks -> certain.
    bool is64 = true;
    {
        const long long* p = (const long long*)ei_raw;
        #pragma unroll
        for (int k = 0; k < 8; ++k) {
            long long x = p[k];
            if (x < 0 || x >= (long long)NN) is64 = false;
        }
    }
    const long long* rows64 = (const long long*)ei_raw;
    const long long* cols64 = rows64 + NE;
    const int*       rows32 = (const int*)ei_raw;
    const int*       cols32 = rows32 + NE;

    // ---- phase 0a: zero degree counts + err slots ----
    for (int i = gtid; i < NN; i += gsize) g_deg[i] = 0;
    for (int i = gtid; i <= MAX_IT; i += gsize) g_err[i] = 0.0f;
    grid_bar(nblocks);

    // ---- phase 0b: pack edges to int2, count out-degrees ----
    if (is64) {
        for (int e = gtid; e < NE; e += gsize) {
            int r = (int)rows64[e];
            int c = (int)cols64[e];
            g_edges[e] = make_int2(r, c);
            atomicAdd(&g_deg[c], 1);
        }
    } else {
        for (int e = gtid; e < NE; e += gsize) {
            int r = rows32[e];
            int c = cols32[e];
            g_edges[e] = make_int2(r, c);
            atomicAdd(&g_deg[c], 1);
        }
    }
    grid_bar(nblocks);

    // ---- phase 0c: per-node weight, init v ----
    for (int i = gtid; i < NN; i += gsize) {
        g_w[i] = 0.85f / (float)g_deg[i];  // inf if deg==0 (never gathered)
        v[i]   = inv_n;
    }
    grid_bar(nblocks);

    // ---- power iterations ----
    for (int it = 0; it < MAX_IT; ++it) {
        // A: y = v*w ; new_v = teleport
        for (int i = gtid; i < NN; i += gsize) {
            g_y[i]  = v[i] * g_w[i];
            g_nv[i] = teleport;
        }
        grid_bar(nblocks);

        // B: SpMV scatter  new_v[row] += y[col]
        for (int e = gtid; e < NE; e += gsize) {
            int2 rc = g_edges[e];
            atomicAdd(&g_nv[rc.x], g_y[rc.y]);
        }
        grid_bar(nblocks);

        // C: err = sum |new_v - v| ; v = new_v
        float local = 0.0f;
        for (int i = gtid; i < NN; i += gsize) {
            float nv = g_nv[i];
            local += fabsf(nv - v[i]);
            v[i] = nv;
        }
        local = block_reduce_sum(local);
        if (threadIdx.x == 0) atomicAdd(&g_err[it], local);
        grid_bar(nblocks);

        // All threads read the same value after the barrier -> same decision.
        float err = *((volatile float*)&g_err[it]);
        if (err < thresh) break;   // this iteration's new_v committed, like ref
    }
}

extern "C" void kernel_launch(void* const* d_in, const int* in_sizes, int n_in,
                              void* d_out, int out_size) {
    (void)in_sizes; (void)n_in; (void)out_size;
    // d_in[0] = x (float32, unused by reference); d_in[1] = edge_index [2, E]
    const void* ei = d_in[1];
    float* v = (float*)d_out;

    int dev = 0;
    cudaGetDevice(&dev);
    int sms = 0;
    cudaDeviceGetAttribute(&sms, cudaDevAttrMultiProcessorCount, dev);
    int maxb = 0;
    cudaOccupancyMaxActiveBlocksPerMultiprocessor(&maxb, pagerank_persistent, 512, 0);
    if (maxb < 1) maxb = 1;
    int nblocks = sms * maxb;   // all co-resident -> grid barrier is safe

    pagerank_persistent<<<nblocks, 512>>>(ei, v, nblocks);
}

// round 3
// speedup vs baseline: 1.0933x; 1.0933x over previous
#include <cuda_runtime.h>
#include <cuda_bf16.h>

#define NN 1000000
#define NE 16000000
#define MAX_IT 100

// ---- device scratch (allocation-free rule: __device__ globals) ----
__device__ int   g_deg[NN];        // out-degree counts
__device__ float g_w[NN];          // alpha / deg
__device__ float g_y[NN];          // v * w  (per-iteration gather source)
__device__ float g_nv[NN];         // new_v accumulator
__device__ float g_err[MAX_IT + 1];
__device__ unsigned g_barcnt;      // grid barrier arrival count
__device__ unsigned g_sense;       // grid barrier generation

// Software grid barrier (all blocks co-resident by construction).
// __threadfence() is gpu-scope -> CCTL.IVALL on sm_103a, so plain loads
// after the barrier observe other SMs' writes (no stale L1).
__device__ __forceinline__ void grid_bar(int nblocks) {
    __syncthreads();
    if (threadIdx.x == 0) {
        unsigned gen = *((volatile unsigned*)&g_sense);
        __threadfence();  // release this block's writes before arriving
        unsigned a = atomicAdd(&g_barcnt, 1u);
        if (a == (unsigned)(nblocks - 1)) {
            g_barcnt = 0;
            __threadfence();
            atomicExch(&g_sense, gen + 1u);
        } else {
            while (*((volatile unsigned*)&g_sense) == gen) { __nanosleep(64); }
        }
        __threadfence();  // acquire: invalidate L1 before post-barrier reads
    }
    __syncthreads();
}

__device__ __forceinline__ float block_reduce_sum(float v) {
    __shared__ float sh[32];
    int lane = threadIdx.x & 31;
    int wid  = threadIdx.x >> 5;
    #pragma unroll
    for (int o = 16; o; o >>= 1) v += __shfl_down_sync(0xffffffffu, v, o);
    if (lane == 0) sh[wid] = v;
    __syncthreads();
    if (wid == 0) {
        v = (lane < (int)(blockDim.x >> 5)) ? sh[lane] : 0.0f;
        #pragma unroll
        for (int o = 16; o; o >>= 1) v += __shfl_down_sync(0xffffffffu, v, o);
    }
    return v;  // valid in warp 0; next grid_bar's __syncthreads guards sh reuse
}

__global__ void __launch_bounds__(512)
pagerank_persistent(const void* __restrict__ ei_raw, float* __restrict__ v,
                    int nblocks) {
    const int gsize = gridDim.x * blockDim.x;
    const int gtid  = blockIdx.x * blockDim.x + threadIdx.x;

    const float inv_n    = 1.0f / (float)NN;
    const float teleport = 0.15f * inv_n;
    const float thresh   = 1000000.0f * 1e-6f;  // N * TOL in float32

    // ---- dtype sniff: int64 vs int32 edge_index -------------------------
    // Genuine int64 indices all lie in [0, NN). An int32 buffer read as
    // int64 pairs gives lo + hi*2^32 (hi random in [0,1M)) -> >= NN almost
    // surely. 8 checks -> decision is certain; identical on every thread.
    bool is64 = true;
    {
        const long long* p = (const long long*)ei_raw;
        #pragma unroll
        for (int k = 0; k < 8; ++k) {
            long long x = p[k];
            if (x < 0 || x >= (long long)NN) is64 = false;
        }
    }
    const long long* rows64 = (const long long*)ei_raw;
    const long long* cols64 = rows64 + NE;
    const int*       rows32 = (const int*)ei_raw;
    const int*       cols32 = rows32 + NE;

    // ---- phase 0a: zero degree counts + err slots ----
    for (int i = gtid; i < NN; i += gsize) g_deg[i] = 0;
    for (int i = gtid; i <= MAX_IT; i += gsize) g_err[i] = 0.0f;
    grid_bar(nblocks);

    // ---- phase 0b: out-degree count (cols only, vectorized) ----
    if (is64) {
        const longlong2* c2 = (const longlong2*)cols64;
        for (int e = gtid; e < NE / 2; e += gsize) {
            longlong2 c = c2[e];
            atomicAdd(&g_deg[(int)c.x], 1);
            atomicAdd(&g_deg[(int)c.y], 1);
        }
    } else {
        const int4* c4 = (const int4*)cols32;
        for (int e = gtid; e < NE / 4; e += gsize) {
            int4 c = c4[e];
            atomicAdd(&g_deg[c.x], 1);
            atomicAdd(&g_deg[c.y], 1);
            atomicAdd(&g_deg[c.z], 1);
            atomicAdd(&g_deg[c.w], 1);
        }
    }
    grid_bar(nblocks);

    // ---- phase 0c: weights + iter-0 state (y0 = inv_n*w, nv = teleport) ----
    for (int i = gtid; i < NN; i += gsize) {
        float w = 0.85f / (float)g_deg[i];  // inf if deg==0 (never gathered)
        g_w[i]  = w;
        v[i]    = inv_n;
        g_y[i]  = inv_n * w;
        g_nv[i] = teleport;
    }
    grid_bar(nblocks);

    // ---- power iterations ----
    for (int it = 0; it < MAX_IT; ++it) {
        // B: SpMV scatter  nv[row] += y[col]   (direct from input, vectorized)
        if (is64) {
            const longlong2* r2 = (const longlong2*)rows64;
            const longlong2* c2 = (const longlong2*)cols64;
            for (int e = gtid; e < NE / 2; e += gsize) {
                longlong2 r = r2[e];
                longlong2 c = c2[e];
                atomicAdd(&g_nv[(int)r.x], g_y[(int)c.x]);
                atomicAdd(&g_nv[(int)r.y], g_y[(int)c.y]);
            }
        } else {
            const int4* r4 = (const int4*)rows32;
            const int4* c4 = (const int4*)cols32;
            for (int e = gtid; e < NE / 4; e += gsize) {
                int4 r = r4[e];
                int4 c = c4[e];
                float y0 = g_y[c.x];
                float y1 = g_y[c.y];
                float y2 = g_y[c.z];
                float y3 = g_y[c.w];
                atomicAdd(&g_nv[r.x], y0);
                atomicAdd(&g_nv[r.y], y1);
                atomicAdd(&g_nv[r.z], y2);
                atomicAdd(&g_nv[r.w], y3);
            }
        }
        grid_bar(nblocks);

        // C (fused with next A): err, commit v, prep y/nv for next iteration
        float local = 0.0f;
        for (int i = gtid; i < NN; i += gsize) {
            float nv = g_nv[i];
            local += fabsf(nv - v[i]);
            v[i]    = nv;
            g_y[i]  = nv * g_w[i];
            g_nv[i] = teleport;
        }
        local = block_reduce_sum(local);
        if (threadIdx.x == 0) atomicAdd(&g_err[it], local);
        grid_bar(nblocks);

        // All threads read the same value after the barrier -> same decision.
        float err = *((volatile float*)&g_err[it]);
        if (err < thresh) break;   // this iteration's new_v committed, like ref
    }
}

extern "C" void kernel_launch(void* const* d_in, const int* in_sizes, int n_in,
                              void* d_out, int out_size) {
    (void)in_sizes; (void)n_in; (void)out_size;
    // d_in[0] = x (float32, unused by reference); d_in[1] = edge_index [2, E]
    const void* ei = d_in[1];
    float* v = (float*)d_out;

    int dev = 0;
    cudaGetDevice(&dev);
    int sms = 0;
    cudaDeviceGetAttribute(&sms, cudaDevAttrMultiProcessorCount, dev);
    int maxb = 0;
    cudaOccupancyMaxActiveBlocksPerMultiprocessor(&maxb, pagerank_persistent, 512, 0);
    if (maxb < 1) maxb = 1;
    int nblocks = sms * maxb;   // all co-resident -> grid barrier is safe

    pagerank_persistent<<<nblocks, 512>>>(ei, v, nblocks);
}

// round 4
// speedup vs baseline: 1.1056x; 1.0112x over previous
#include <cuda_runtime.h>
#include <cuda_bf16.h>

#define NN 1000000
#define NE 16000000
#define MAX_IT 100

// ---- device scratch (allocation-free rule: __device__ globals) ----
__device__ int   g_deg[NN];        // out-degree counts
__device__ float g_w[NN];          // alpha / deg
__device__ float g_y[NN];          // v * w  (per-iteration gather source)
__device__ float g_nv[NN];         // new_v accumulator
__device__ float g_err[MAX_IT + 1];
__device__ unsigned g_barcnt;      // grid barrier arrival count
__device__ unsigned g_sense;       // grid barrier generation

// Software grid barrier (all blocks co-resident by construction).
// __threadfence() is gpu-scope -> CCTL.IVALL on sm_103a, so plain loads
// after the barrier observe other SMs' writes (no stale L1).
__device__ __forceinline__ void grid_bar(int nblocks) {
    __syncthreads();
    if (threadIdx.x == 0) {
        unsigned gen = *((volatile unsigned*)&g_sense);
        __threadfence();  // release this block's writes before arriving
        unsigned a = atomicAdd(&g_barcnt, 1u);
        if (a == (unsigned)(nblocks - 1)) {
            g_barcnt = 0;
            __threadfence();
            atomicExch(&g_sense, gen + 1u);
        } else {
            while (*((volatile unsigned*)&g_sense) == gen) { __nanosleep(64); }
        }
        __threadfence();  // acquire: invalidate L1 before post-barrier reads
    }
    __syncthreads();
}

__device__ __forceinline__ float block_reduce_sum(float v) {
    __shared__ float sh[32];
    int lane = threadIdx.x & 31;
    int wid  = threadIdx.x >> 5;
    #pragma unroll
    for (int o = 16; o; o >>= 1) v += __shfl_down_sync(0xffffffffu, v, o);
    if (lane == 0) sh[wid] = v;
    __syncthreads();
    if (wid == 0) {
        v = (lane < (int)(blockDim.x >> 5)) ? sh[lane] : 0.0f;
        #pragma unroll
        for (int o = 16; o; o >>= 1) v += __shfl_down_sync(0xffffffffu, v, o);
    }
    return v;  // valid in warp 0; next grid_bar's __syncthreads guards sh reuse
}

__global__ void __launch_bounds__(512, 4)   // force <=32 regs -> 2048 thr/SM
pagerank_persistent(const void* __restrict__ ei_raw, float* __restrict__ v,
                    int nblocks) {
    const int gsize = gridDim.x * blockDim.x;
    const int gtid  = blockIdx.x * blockDim.x + threadIdx.x;

    const float inv_n    = 1.0f / (float)NN;
    const float teleport = 0.15f * inv_n;
    const float thresh   = 1000000.0f * 1e-6f;  // N * TOL in float32

    // ---- dtype sniff: int64 vs int32 edge_index -------------------------
    // Genuine int64 indices all lie in [0, NN). An int32 buffer read as
    // int64 pairs gives lo + hi*2^32 (hi random in [0,1M)) -> >= NN almost
    // surely. 8 checks -> decision is certain; identical on every thread.
    bool is64 = true;
    {
        const long long* p = (const long long*)ei_raw;
        #pragma unroll
        for (int k = 0; k < 8; ++k) {
            long long x = p[k];
            if (x < 0 || x >= (long long)NN) is64 = false;
        }
    }
    const long long* rows64 = (const long long*)ei_raw;
    const long long* cols64 = rows64 + NE;
    const int*       rows32 = (const int*)ei_raw;
    const int*       cols32 = rows32 + NE;

    // ---- phase 0a: zero degree counts + err slots ----
    for (int i = gtid; i < NN; i += gsize) g_deg[i] = 0;
    for (int i = gtid; i <= MAX_IT; i += gsize) g_err[i] = 0.0f;
    grid_bar(nblocks);

    // ---- phase 0b: out-degree count (cols only, vectorized) ----
    if (is64) {
        const longlong2* c2 = (const longlong2*)cols64;
        #pragma unroll 2
        for (int e = gtid; e < NE / 2; e += gsize) {
            longlong2 c = c2[e];
            atomicAdd(&g_deg[(int)c.x], 1);
            atomicAdd(&g_deg[(int)c.y], 1);
        }
    } else {
        const int4* c4 = (const int4*)cols32;
        #pragma unroll 2
        for (int e = gtid; e < NE / 4; e += gsize) {
            int4 c = c4[e];
            atomicAdd(&g_deg[c.x], 1);
            atomicAdd(&g_deg[c.y], 1);
            atomicAdd(&g_deg[c.z], 1);
            atomicAdd(&g_deg[c.w], 1);
        }
    }
    grid_bar(nblocks);

    // ---- phase 0c: weights + iter-0 state (y0 = inv_n*w, nv = teleport) ----
    for (int i = gtid; i < NN; i += gsize) {
        float w = 0.85f / (float)g_deg[i];  // inf if deg==0 (never gathered)
        g_w[i]  = w;
        v[i]    = inv_n;
        g_y[i]  = inv_n * w;
        g_nv[i] = teleport;
    }
    grid_bar(nblocks);

    // ---- power iterations ----
    for (int it = 0; it < MAX_IT; ++it) {
        // B: SpMV scatter  nv[row] += y[col]   (direct from input; loads
        // batched so 4-8 gathers are in flight before the REDG stream)
        if (is64) {
            const longlong2* r2 = (const longlong2*)rows64;
            const longlong2* c2 = (const longlong2*)cols64;
            #pragma unroll 2
            for (int e = gtid; e < NE / 2; e += gsize) {
                longlong2 r = r2[e];
                longlong2 c = c2[e];
                float y0 = g_y[(int)c.x];
                float y1 = g_y[(int)c.y];
                atomicAdd(&g_nv[(int)r.x], y0);
                atomicAdd(&g_nv[(int)r.y], y1);
            }
        } else {
            const int4* r4 = (const int4*)rows32;
            const int4* c4 = (const int4*)cols32;
            #pragma unroll 2
            for (int e = gtid; e < NE / 4; e += gsize) {
                int4 r = r4[e];
                int4 c = c4[e];
                float y0 = g_y[c.x];
                float y1 = g_y[c.y];
                float y2 = g_y[c.z];
                float y3 = g_y[c.w];
                atomicAdd(&g_nv[r.x], y0);
                atomicAdd(&g_nv[r.y], y1);
                atomicAdd(&g_nv[r.z], y2);
                atomicAdd(&g_nv[r.w], y3);
            }
        }
        grid_bar(nblocks);

        // C (fused with next A): err, commit v, prep y/nv for next iteration
        float local = 0.0f;
        for (int i = gtid; i < NN; i += gsize) {
            float nv = g_nv[i];
            local += fabsf(nv - v[i]);
            v[i]    = nv;
            g_y[i]  = nv * g_w[i];
            g_nv[i] = teleport;
        }
        local = block_reduce_sum(local);
        if (threadIdx.x == 0) atomicAdd(&g_err[it], local);
        grid_bar(nblocks);

        // All threads read the same value after the barrier -> same decision.
        float err = *((volatile float*)&g_err[it]);
        if (err < thresh) break;   // this iteration's new_v committed, like ref
    }
}

extern "C" void kernel_launch(void* const* d_in, const int* in_sizes, int n_in,
                              void* d_out, int out_size) {
    (void)in_sizes; (void)n_in; (void)out_size;
    // d_in[0] = x (float32, unused by reference); d_in[1] = edge_index [2, E]
    const void* ei = d_in[1];
    float* v = (float*)d_out;

    int dev = 0;
    cudaGetDevice(&dev);
    int sms = 0;
    cudaDeviceGetAttribute(&sms, cudaDevAttrMultiProcessorCount, dev);
    int maxb = 0;
    cudaOccupancyMaxActiveBlocksPerMultiprocessor(&maxb, pagerank_persistent, 512, 0);
    if (maxb < 1) maxb = 1;
    int nblocks = sms * maxb;   // all co-resident -> grid barrier is safe

    pagerank_persistent<<<nblocks, 512>>>(ei, v, nblocks);
}

// round 5
// speedup vs baseline: 1.1214x; 1.0143x over previous
#include <cuda_runtime.h>
#include <cuda_bf16.h>

#define NN 1000000
#define NE 16000000
#define MAX_IT 100

// ---- device scratch (allocation-free rule: __device__ globals) ----
__device__ int   g_deg[NN];        // out-degree counts
__device__ float g_w[NN];          // alpha / deg
__device__ float g_y[NN];          // v * w  (per-iteration gather source)
__device__ float g_nv[NN];         // new_v accumulator
__device__ float g_err[MAX_IT + 1];
__device__ unsigned g_barcnt;      // grid barrier arrival count
__device__ unsigned g_sense;       // grid barrier generation

// Software grid barrier (all blocks co-resident by construction).
__device__ __forceinline__ void grid_bar(int nblocks) {
    __syncthreads();
    if (threadIdx.x == 0) {
        unsigned gen = *((volatile unsigned*)&g_sense);
        __threadfence();  // release
        unsigned a = atomicAdd(&g_barcnt, 1u);
        if (a == (unsigned)(nblocks - 1)) {
            g_barcnt = 0;
            __threadfence();
            atomicExch(&g_sense, gen + 1u);
        } else {
            while (*((volatile unsigned*)&g_sense) == gen) { __nanosleep(64); }
        }
        __threadfence();  // acquire (CCTL.IVALL: flush L1 before reads)
    }
    __syncthreads();
}

__device__ __forceinline__ float block_reduce_sum(float v) {
    __shared__ float sh[32];
    int lane = threadIdx.x & 31;
    int wid  = threadIdx.x >> 5;
    #pragma unroll
    for (int o = 16; o; o >>= 1) v += __shfl_down_sync(0xffffffffu, v, o);
    if (lane == 0) sh[wid] = v;
    __syncthreads();
    if (wid == 0) {
        v = (lane < (int)(blockDim.x >> 5)) ? sh[lane] : 0.0f;
        #pragma unroll
        for (int o = 16; o; o >>= 1) v += __shfl_down_sync(0xffffffffu, v, o);
    }
    return v;
}

__global__ void __launch_bounds__(512, 3)   // <=42 regs; MLP > occupancy here
pagerank_persistent(const void* __restrict__ ei_raw, float* __restrict__ v,
                    int nblocks) {
    const int gsize = gridDim.x * blockDim.x;
    const int gtid  = blockIdx.x * blockDim.x + threadIdx.x;

    const float inv_n    = 1.0f / (float)NN;
    const float teleport = 0.15f * inv_n;
    const float thresh   = 1000000.0f * 1e-6f;  // N * TOL in float32

    // ---- dtype sniff: int64 vs int32 edge_index (certain after 8 checks) --
    bool is64 = true;
    {
        const long long* p = (const long long*)ei_raw;
        #pragma unroll
        for (int k = 0; k < 8; ++k) {
            long long x = p[k];
            if (x < 0 || x >= (long long)NN) is64 = false;
        }
    }
    const long long* rows64 = (const long long*)ei_raw;
    const long long* cols64 = rows64 + NE;
    const int*       rows32 = (const int*)ei_raw;
    const int*       cols32 = rows32 + NE;

    // ---- phase 0a: zero degree counts + err slots ----
    for (int i = gtid; i < NN; i += gsize) g_deg[i] = 0;
    for (int i = gtid; i <= MAX_IT; i += gsize) g_err[i] = 0.0f;
    grid_bar(nblocks);

    // ---- phase 0b: out-degree count, 8-edge batches ----
    if (is64) {
        const int4* c4 = (const int4*)cols64;  // int4 = 2 int64 cols
        for (int e = gtid; e < NE / 8; e += gsize) {
            int4 a = __ldcs(&c4[4*e + 0]);
            int4 b = __ldcs(&c4[4*e + 1]);
            int4 c = __ldcs(&c4[4*e + 2]);
            int4 d = __ldcs(&c4[4*e + 3]);
            atomicAdd(&g_deg[a.x], 1); atomicAdd(&g_deg[a.z], 1);
            atomicAdd(&g_deg[b.x], 1); atomicAdd(&g_deg[b.z], 1);
            atomicAdd(&g_deg[c.x], 1); atomicAdd(&g_deg[c.z], 1);
            atomicAdd(&g_deg[d.x], 1); atomicAdd(&g_deg[d.z], 1);
        }
    } else {
        const int4* c4 = (const int4*)cols32;
        for (int e = gtid; e < NE / 8; e += gsize) {
            int4 a = __ldcs(&c4[2*e + 0]);
            int4 b = __ldcs(&c4[2*e + 1]);
            atomicAdd(&g_deg[a.x], 1); atomicAdd(&g_deg[a.y], 1);
            atomicAdd(&g_deg[a.z], 1); atomicAdd(&g_deg[a.w], 1);
            atomicAdd(&g_deg[b.x], 1); atomicAdd(&g_deg[b.y], 1);
            atomicAdd(&g_deg[b.z], 1); atomicAdd(&g_deg[b.w], 1);
        }
    }
    grid_bar(nblocks);

    // ---- phase 0c: weights + iter-0 state (y0 = inv_n*w, nv = teleport) ----
    for (int i = gtid; i < NN; i += gsize) {
        float w = 0.85f / (float)g_deg[i];  // inf if deg==0 (never gathered)
        g_w[i]  = w;
        g_y[i]  = inv_n * w;
        g_nv[i] = teleport;
    }
    grid_bar(nblocks);

    // ---- power iterations ----
    for (int it = 0; it < MAX_IT; ++it) {
        // B: SpMV scatter nv[row] += y[col], 8-edge software pipeline:
        // all streams -> all gathers -> all fire-and-forget REDs.
        if (is64) {
            const int4* r4 = (const int4*)rows64;
            const int4* c4 = (const int4*)cols64;
            for (int e = gtid; e < NE / 8; e += gsize) {
                int4 ca = __ldcs(&c4[4*e+0]); int4 cb = __ldcs(&c4[4*e+1]);
                int4 cc = __ldcs(&c4[4*e+2]); int4 cd = __ldcs(&c4[4*e+3]);
                int4 ra = __ldcs(&r4[4*e+0]); int4 rb = __ldcs(&r4[4*e+1]);
                int4 rc = __ldcs(&r4[4*e+2]); int4 rd = __ldcs(&r4[4*e+3]);
                float y0 = __ldcg(&g_y[ca.x]), y1 = __ldcg(&g_y[ca.z]);
                float y2 = __ldcg(&g_y[cb.x]), y3 = __ldcg(&g_y[cb.z]);
                float y4 = __ldcg(&g_y[cc.x]), y5 = __ldcg(&g_y[cc.z]);
                float y6 = __ldcg(&g_y[cd.x]), y7 = __ldcg(&g_y[cd.z]);
                atomicAdd(&g_nv[ra.x], y0); atomicAdd(&g_nv[ra.z], y1);
                atomicAdd(&g_nv[rb.x], y2); atomicAdd(&g_nv[rb.z], y3);
                atomicAdd(&g_nv[rc.x], y4); atomicAdd(&g_nv[rc.z], y5);
                atomicAdd(&g_nv[rd.x], y6); atomicAdd(&g_nv[rd.z], y7);
            }
        } else {
            const int4* r4 = (const int4*)rows32;
            const int4* c4 = (const int4*)cols32;
            for (int e = gtid; e < NE / 8; e += gsize) {
                int4 ca = __ldcs(&c4[2*e+0]); int4 cb = __ldcs(&c4[2*e+1]);
                int4 ra = __ldcs(&r4[2*e+0]); int4 rb = __ldcs(&r4[2*e+1]);
                float y0 = __ldcg(&g_y[ca.x]), y1 = __ldcg(&g_y[ca.y]);
                float y2 = __ldcg(&g_y[ca.z]), y3 = __ldcg(&g_y[ca.w]);
                float y4 = __ldcg(&g_y[cb.x]), y5 = __ldcg(&g_y[cb.y]);
                float y6 = __ldcg(&g_y[cb.z]), y7 = __ldcg(&g_y[cb.w]);
                atomicAdd(&g_nv[ra.x], y0); atomicAdd(&g_nv[ra.y], y1);
                atomicAdd(&g_nv[ra.z], y2); atomicAdd(&g_nv[ra.w], y3);
                atomicAdd(&g_nv[rb.x], y4); atomicAdd(&g_nv[rb.y], y5);
                atomicAdd(&g_nv[rb.z], y6); atomicAdd(&g_nv[rb.w], y7);
            }
        }
        grid_bar(nblocks);

        // C1: err + commit v (old v for it 0 is the constant inv_n)
        float local = 0.0f;
        if (it == 0) {
            for (int i = gtid; i < NN; i += gsize) {
                float nv = g_nv[i];
                local += fabsf(nv - inv_n);
                v[i] = nv;
            }
        } else {
            for (int i = gtid; i < NN; i += gsize) {
                float nv = g_nv[i];
                local += fabsf(nv - v[i]);
                v[i] = nv;
            }
        }
        local = block_reduce_sum(local);
        if (threadIdx.x == 0) atomicAdd(&g_err[it], local);
        grid_bar(nblocks);

        float err = *((volatile float*)&g_err[it]);
        if (err < thresh) break;   // committed this iteration's new_v, like ref

        // C2: only if continuing — prep y/nv for next iteration
        for (int i = gtid; i < NN; i += gsize) {
            float nv = v[i];
            g_y[i]  = nv * g_w[i];
            g_nv[i] = teleport;
        }
        grid_bar(nblocks);
    }
}

extern "C" void kernel_launch(void* const* d_in, const int* in_sizes, int n_in,
                              void* d_out, int out_size) {
    (void)in_sizes; (void)n_in; (void)out_size;
    const void* ei = d_in[1];
    float* v = (float*)d_out;

    int dev = 0;
    cudaGetDevice(&dev);
    int sms = 0;
    cudaDeviceGetAttribute(&sms, cudaDevAttrMultiProcessorCount, dev);
    int maxb = 0;
    cudaOccupancyMaxActiveBlocksPerMultiprocessor(&maxb, pagerank_persistent, 512, 0);
    if (maxb < 1) maxb = 1;
    int nblocks = sms * maxb;   // all co-resident -> grid barrier is safe

    pagerank_persistent<<<nblocks, 512>>>(ei, v, nblocks);
}